// round 16
// baseline (speedup 1.0000x reference)
#include <cuda_runtime.h>
#include <cuda_fp16.h>
#include <cstdint>

#define N_PTS 100000
#define KNN   16
#define NK    (N_PTS * KNN)
#define EPSB  1e-5f

// ---------------- scratch (static device memory; no dynamic alloc) ----------
__device__ int    g_counts[N_PTS];
__device__ float  g_y1[(size_t)N_PTS * 64];    // pre-BN layer-1 output (fp32)
__device__ __half g_z[(size_t)N_PTS * 128];    // pre-BN layer-2 output (fp16)
__device__ float  g_stats1[2 * 64];            // weighted sum, sumsq
__device__ float  g_stats2[2 * 128];

// ---------------- packed f32x2 helpers --------------------------------------
__device__ __forceinline__ unsigned long long pack2s(float a) {
    unsigned long long r;
    asm("mov.b64 %0, {%1, %1};" : "=l"(r) : "f"(a));
    return r;
}
__device__ __forceinline__ float2 unpack2(unsigned long long v) {
    float2 r;
    asm("mov.b64 {%0, %1}, %2;" : "=f"(r.x), "=f"(r.y) : "l"(v));
    return r;
}
__device__ __forceinline__ void fma2(unsigned long long& d,
                                     unsigned long long a,
                                     unsigned long long b) {
    asm("fma.rn.f32x2 %0, %1, %2, %0;" : "+l"(d) : "l"(a), "l"(b));
}
__device__ __forceinline__ float felem(const float4& v, int k) {
    return (k == 0) ? v.x : (k == 1) ? v.y : (k == 2) ? v.z : v.w;
}

// ---------------- small kernels ----------------------------------------------
__global__ void zero_kernel() {
    int i = blockIdx.x * blockDim.x + threadIdx.x;
    if (i < N_PTS) g_counts[i] = 0;
    if (i < 2 * 64) g_stats1[i] = 0.f;
    if (i < 2 * 128) g_stats2[i] = 0.f;
}

__global__ void count_kernel(const int4* __restrict__ idx4) {
    int i = blockIdx.x * blockDim.x + threadIdx.x;
    if (i < NK / 4) {
        int4 v = idx4[i];
        atomicAdd(&g_counts[v.x], 1);
        atomicAdd(&g_counts[v.y], 1);
        atomicAdd(&g_counts[v.z], 1);
        atomicAdd(&g_counts[v.w], 1);
    }
}

// GEMM1: y1 = feat @ W1 + b1 ; weighted BN1 stats.
// Block: 64 rows x 64 cols, 128 threads as 8(tx) x 16(ty); 6 CTAs/SM.
// Thread tile: 4 rows x 8 cols ({tx*4..+3, 32+tx*4..+3}).
// A in smem with XOR-swizzled 16B granules: granule sg = k4 ^ ((r>>2)&7)
// -> conflict-free float4 A loads across the warp's 4 ty values.
__global__ __launch_bounds__(128, 6) void gemm1_kernel(const float* __restrict__ feat,
                                                       const float* __restrict__ W1,
                                                       const float* __restrict__ b1) {
    __shared__ float As[64 * 64];        // 16 KB, swizzled [row][granule]
    __shared__ float Bs[64 * 64];        // 16 KB, [k][col]
    const int tid = threadIdx.x;
    const int tx = tid & 7, ty = tid >> 3;     // ty 0..15
    const int row0 = blockIdx.x * 64;

#pragma unroll
    for (int it = 0; it < 8; it++) {
        int f = tid + it * 128;
        ((float4*)Bs)[f] = ((const float4*)W1)[f];
    }
#pragma unroll
    for (int it = 0; it < 8; it++) {
        int f = tid + it * 128;          // [0, 1024)
        int r = f >> 4, k4 = f & 15;
        int grow = row0 + r;
        float4 v = (grow < N_PTS) ? ((const float4*)feat)[grow * 16 + k4]
                                  : make_float4(0.f, 0.f, 0.f, 0.f);
        int sg = k4 ^ ((r >> 2) & 7);
        *(float4*)&As[r * 64 + sg * 4] = v;
    }
    __syncthreads();

    unsigned long long acc[4][4];
#pragma unroll
    for (int i = 0; i < 4; i++)
#pragma unroll
        for (int j = 0; j < 4; j++) acc[i][j] = 0ull;

    const int rx = ty & 7;   // (ri>>2)&7 is identical for this thread's 4 rows
#pragma unroll
    for (int kk4 = 0; kk4 < 16; kk4++) {
        float4 a[4];
        const int sg = (kk4 ^ rx) * 4;
#pragma unroll
        for (int i = 0; i < 4; i++)
            a[i] = *(const float4*)&As[(ty * 4 + i) * 64 + sg];
#pragma unroll
        for (int kq = 0; kq < 4; kq++) {
            const ulonglong2 bA = *(const ulonglong2*)&Bs[(kk4 * 4 + kq) * 64 + tx * 4];
            const ulonglong2 bB = *(const ulonglong2*)&Bs[(kk4 * 4 + kq) * 64 + 32 + tx * 4];
#pragma unroll
            for (int i = 0; i < 4; i++) {
                unsigned long long ad = pack2s(felem(a[i], kq));
                fma2(acc[i][0], ad, bA.x);
                fma2(acc[i][1], ad, bA.y);
                fma2(acc[i][2], ad, bB.x);
                fma2(acc[i][3], ad, bB.y);
            }
        }
    }

    const float4 biasA = *(const float4*)&b1[tx * 4];
    const float4 biasB = *(const float4*)&b1[32 + tx * 4];
    float ws[8], wq[8];
#pragma unroll
    for (int j = 0; j < 8; j++) { ws[j] = 0.f; wq[j] = 0.f; }
#pragma unroll
    for (int i = 0; i < 4; i++) {
        int grow = row0 + ty * 4 + i;
        if (grow >= N_PTS) continue;
        float2 p0 = unpack2(acc[i][0]);
        float2 p1 = unpack2(acc[i][1]);
        float2 p2 = unpack2(acc[i][2]);
        float2 p3 = unpack2(acc[i][3]);
        float y[8];
        y[0] = p0.x + biasA.x; y[1] = p0.y + biasA.y;
        y[2] = p1.x + biasA.z; y[3] = p1.y + biasA.w;
        y[4] = p2.x + biasB.x; y[5] = p2.y + biasB.y;
        y[6] = p3.x + biasB.z; y[7] = p3.y + biasB.w;
        *(float4*)&g_y1[(size_t)grow * 64 + tx * 4] = make_float4(y[0], y[1], y[2], y[3]);
        *(float4*)&g_y1[(size_t)grow * 64 + 32 + tx * 4] = make_float4(y[4], y[5], y[6], y[7]);
        float w = (float)g_counts[grow];
#pragma unroll
        for (int j = 0; j < 8; j++) {
            ws[j] += w * y[j];
            wq[j] += w * y[j] * y[j];
        }
    }
    __syncthreads();
    float* red = As;   // 4096 floats; need 2 * 1024 -> use [0,1024) and [1024,2048)
#pragma unroll
    for (int j = 0; j < 4; j++) {
        red[ty * 64 + tx * 4 + j] = ws[j];
        red[ty * 64 + 32 + tx * 4 + j] = ws[4 + j];
        red[1024 + ty * 64 + tx * 4 + j] = wq[j];
        red[1024 + ty * 64 + 32 + tx * 4 + j] = wq[4 + j];
    }
    __syncthreads();
    if (tid < 64) {
        float s = 0.f, q = 0.f;
#pragma unroll
        for (int t = 0; t < 16; t++) {
            s += red[t * 64 + tid];
            q += red[1024 + t * 64 + tid];
        }
        atomicAdd(&g_stats1[tid], s);
        atomicAdd(&g_stats1[64 + tid], q);
    }
}

// GEMM2: h = relu(bn1(y1)); y2 = h @ W2 + b2 -> fp16 g_z; weighted BN2 stats.
// Same crossbar-optimal shape + swizzle as gemm1; blockIdx.y = N-half.
__global__ __launch_bounds__(128, 6) void gemm2_kernel(const float* __restrict__ W2,
                                                       const float* __restrict__ b2,
                                                       const float* __restrict__ gamma1,
                                                       const float* __restrict__ beta1) {
    __shared__ float As[64 * 64];        // 16 KB, swizzled [row][granule]
    __shared__ float Bs[64 * 64];        // 16 KB, [k][col-half]
    __shared__ float sb1s[128];
    const int tid = threadIdx.x;
    const int tx = tid & 7, ty = tid >> 3;     // ty 0..15
    const int row0 = blockIdx.x * 64;
    const int col0 = blockIdx.y * 64;

    if (tid < 64) {
        const float inv_m = 1.0f / (float)NK;
        float mean = g_stats1[tid] * inv_m;
        float var = g_stats1[64 + tid] * inv_m - mean * mean;
        float sc = gamma1[tid] * rsqrtf(var + EPSB);
        sb1s[tid] = sc;
        sb1s[64 + tid] = beta1[tid] - mean * sc;
    }
    // B half: Bs[k][0..63] = W2[k][col0..col0+63]
#pragma unroll
    for (int it = 0; it < 8; it++) {
        int f = tid + it * 128;           // k = f>>4, c4 = f&15
        int k = f >> 4, c4 = f & 15;
        ((float4*)Bs)[f] = *(const float4*)&W2[k * 128 + col0 + c4 * 4];
    }
    __syncthreads();   // sb1s ready

#pragma unroll
    for (int it = 0; it < 8; it++) {
        int f = tid + it * 128;          // [0, 1024)
        int r = f >> 4, k4 = f & 15;
        int grow = row0 + r;
        float4 v = (grow < N_PTS) ? ((const float4*)g_y1)[grow * 16 + k4]
                                  : make_float4(0.f, 0.f, 0.f, 0.f);
        float4 s = *(const float4*)&sb1s[k4 * 4];
        float4 bb = *(const float4*)&sb1s[64 + k4 * 4];
        v.x = fmaxf(fmaf(v.x, s.x, bb.x), 0.f);
        v.y = fmaxf(fmaf(v.y, s.y, bb.y), 0.f);
        v.z = fmaxf(fmaf(v.z, s.z, bb.z), 0.f);
        v.w = fmaxf(fmaf(v.w, s.w, bb.w), 0.f);
        int sg = k4 ^ ((r >> 2) & 7);
        *(float4*)&As[r * 64 + sg * 4] = v;
    }
    __syncthreads();

    unsigned long long acc[4][4];
#pragma unroll
    for (int i = 0; i < 4; i++)
#pragma unroll
        for (int j = 0; j < 4; j++) acc[i][j] = 0ull;

    const int rx = ty & 7;
#pragma unroll
    for (int kk4 = 0; kk4 < 16; kk4++) {
        float4 a[4];
        const int sg = (kk4 ^ rx) * 4;
#pragma unroll
        for (int i = 0; i < 4; i++)
            a[i] = *(const float4*)&As[(ty * 4 + i) * 64 + sg];
#pragma unroll
        for (int kq = 0; kq < 4; kq++) {
            const ulonglong2 bA = *(const ulonglong2*)&Bs[(kk4 * 4 + kq) * 64 + tx * 4];
            const ulonglong2 bB = *(const ulonglong2*)&Bs[(kk4 * 4 + kq) * 64 + 32 + tx * 4];
#pragma unroll
            for (int i = 0; i < 4; i++) {
                unsigned long long ad = pack2s(felem(a[i], kq));
                fma2(acc[i][0], ad, bA.x);
                fma2(acc[i][1], ad, bA.y);
                fma2(acc[i][2], ad, bB.x);
                fma2(acc[i][3], ad, bB.y);
            }
        }
    }

    const float4 biasA = *(const float4*)&b2[col0 + tx * 4];
    const float4 biasB = *(const float4*)&b2[col0 + 32 + tx * 4];
    float ws[8], wq[8];
#pragma unroll
    for (int j = 0; j < 8; j++) { ws[j] = 0.f; wq[j] = 0.f; }
#pragma unroll
    for (int i = 0; i < 4; i++) {
        int grow = row0 + ty * 4 + i;
        if (grow >= N_PTS) continue;
        float2 p0 = unpack2(acc[i][0]);
        float2 p1 = unpack2(acc[i][1]);
        float2 p2 = unpack2(acc[i][2]);
        float2 p3 = unpack2(acc[i][3]);
        float y[8];
        y[0] = p0.x + biasA.x; y[1] = p0.y + biasA.y;
        y[2] = p1.x + biasA.z; y[3] = p1.y + biasA.w;
        y[4] = p2.x + biasB.x; y[5] = p2.y + biasB.y;
        y[6] = p3.x + biasB.z; y[7] = p3.y + biasB.w;
        __half2 h0 = __floats2half2_rn(y[0], y[1]);
        __half2 h1 = __floats2half2_rn(y[2], y[3]);
        __half2 h2 = __floats2half2_rn(y[4], y[5]);
        __half2 h3 = __floats2half2_rn(y[6], y[7]);
        uint2 hv0, hv1;
        hv0.x = *(uint32_t*)&h0; hv0.y = *(uint32_t*)&h1;
        hv1.x = *(uint32_t*)&h2; hv1.y = *(uint32_t*)&h3;
        *(uint2*)&g_z[(size_t)grow * 128 + col0 + tx * 4] = hv0;
        *(uint2*)&g_z[(size_t)grow * 128 + col0 + 32 + tx * 4] = hv1;
        float w = (float)g_counts[grow];
#pragma unroll
        for (int j = 0; j < 8; j++) {
            ws[j] += w * y[j];
            wq[j] += w * y[j] * y[j];
        }
    }
    __syncthreads();
    float* red = As;
#pragma unroll
    for (int j = 0; j < 4; j++) {
        red[ty * 64 + tx * 4 + j] = ws[j];
        red[ty * 64 + 32 + tx * 4 + j] = ws[4 + j];
        red[1024 + ty * 64 + tx * 4 + j] = wq[j];
        red[1024 + ty * 64 + 32 + tx * 4 + j] = wq[4 + j];
    }
    __syncthreads();
    if (tid < 64) {
        float s = 0.f, q = 0.f;
#pragma unroll
        for (int t = 0; t < 16; t++) {
            s += red[t * 64 + tid];
            q += red[1024 + t * 64 + tid];
        }
        atomicAdd(&g_stats2[col0 + tid], s);
        atomicAdd(&g_stats2[128 + col0 + tid], q);
    }
}

// Final gather + max/min-pool over pre-BN fp16 table, then folded BN2
// affine + ReLU (per-thread from g_stats2). One warp = TWO points.
__global__ __launch_bounds__(256) void gather_max_kernel(
    const int* __restrict__ idx, const float* __restrict__ gamma2,
    const float* __restrict__ beta2, float* __restrict__ out) {
    int warp = (blockIdx.x * blockDim.x + threadIdx.x) >> 5;
    int lane = threadIdx.x & 31;
    int p = warp * 2 + (lane >> 4);
    if (p >= N_PTS) return;
    int half_lane = lane & 15;
    int c0 = half_lane * 8;

    int myidx = idx[p * 16 + half_lane];

    __half2 mx[4], mn[4];
#pragma unroll
    for (int j = 0; j < 4; j++) {
        mx[j] = __floats2half2_rn(-65504.f, -65504.f);
        mn[j] = __floats2half2_rn(65504.f, 65504.f);
    }

#pragma unroll
    for (int k = 0; k < 16; k++) {
        int r = __shfl_sync(0xffffffffu, myidx, (lane & 16) + k);
        uint4 raw = *(const uint4*)&g_z[(size_t)r * 128 + c0];
        __half2 v[4];
        *(uint4*)v = raw;
        mx[0] = __hmax2(mx[0], v[0]); mn[0] = __hmin2(mn[0], v[0]);
        mx[1] = __hmax2(mx[1], v[1]); mn[1] = __hmin2(mn[1], v[1]);
        mx[2] = __hmax2(mx[2], v[2]); mn[2] = __hmin2(mn[2], v[2]);
        mx[3] = __hmax2(mx[3], v[3]); mn[3] = __hmin2(mn[3], v[3]);
    }

    const float inv_m = 1.0f / (float)NK;
    float4 sum0 = *(const float4*)&g_stats2[c0];
    float4 sum1 = *(const float4*)&g_stats2[c0 + 4];
    float4 sq0 = *(const float4*)&g_stats2[128 + c0];
    float4 sq1 = *(const float4*)&g_stats2[128 + c0 + 4];
    float4 gm0 = *(const float4*)&gamma2[c0];
    float4 gm1 = *(const float4*)&gamma2[c0 + 4];
    float4 bt0 = *(const float4*)&beta2[c0];
    float4 bt1 = *(const float4*)&beta2[c0 + 4];
    float sm[8] = {sum0.x, sum0.y, sum0.z, sum0.w, sum1.x, sum1.y, sum1.z, sum1.w};
    float sq[8] = {sq0.x, sq0.y, sq0.z, sq0.w, sq1.x, sq1.y, sq1.z, sq1.w};
    float gm[8] = {gm0.x, gm0.y, gm0.z, gm0.w, gm1.x, gm1.y, gm1.z, gm1.w};
    float bt[8] = {bt0.x, bt0.y, bt0.z, bt0.w, bt1.x, bt1.y, bt1.z, bt1.w};

    float o[8];
#pragma unroll
    for (int j = 0; j < 8; j++) {
        float mean = sm[j] * inv_m;
        float var = sq[j] * inv_m - mean * mean;
        float sc = gm[j] * rsqrtf(var + EPSB);
        float bi = bt[j] - mean * sc;
        float2 fx = __half22float2(mx[j >> 1]);
        float2 fn = __half22float2(mn[j >> 1]);
        float vx = (j & 1) ? fx.y : fx.x;
        float vn = (j & 1) ? fn.y : fn.x;
        float m = (sc >= 0.f) ? vx : vn;
        o[j] = fmaxf(fmaf(sc, m, bi), 0.f);
    }
    size_t off = (size_t)p * 128 + c0;
    *(float4*)&out[off]     = make_float4(o[0], o[1], o[2], o[3]);
    *(float4*)&out[off + 4] = make_float4(o[4], o[5], o[6], o[7]);
}

// ---------------- launch ------------------------------------------------------
extern "C" void kernel_launch(void* const* d_in, const int* in_sizes, int n_in,
                              void* d_out, int out_size) {
    const float* feat = (const float*)d_in[0];
    const int* idx = (const int*)d_in[1];
    const float* W1 = (const float*)d_in[2];
    const float* b1 = (const float*)d_in[3];
    const float* g1 = (const float*)d_in[4];
    const float* be1 = (const float*)d_in[5];
    const float* W2 = (const float*)d_in[6];
    const float* b2 = (const float*)d_in[7];
    const float* g2 = (const float*)d_in[8];
    const float* be2 = (const float*)d_in[9];
    float* out = (float*)d_out;

    zero_kernel<<<(N_PTS + 255) / 256, 256>>>();
    count_kernel<<<(NK / 4 + 255) / 256, 256>>>((const int4*)idx);
    gemm1_kernel<<<(N_PTS + 63) / 64, 128>>>(feat, W1, b1);
    dim3 g2grid((N_PTS + 63) / 64, 2);
    gemm2_kernel<<<g2grid, 128>>>(W2, b2, g1, be1);
    gather_max_kernel<<<(N_PTS * 16 + 255) / 256, 256>>>(idx, g2, be2, out);
}

// round 17
// speedup vs baseline: 1.0375x; 1.0375x over previous
#include <cuda_runtime.h>
#include <cuda_fp16.h>
#include <cstdint>

#define N_PTS 100000
#define KNN   16
#define NK    (N_PTS * KNN)
#define EPSB  1e-5f
#define ASTRIDE 68   // padded A row stride (floats) -> conflict-free broadcasts

// ---------------- scratch (static device memory; no dynamic alloc) ----------
__device__ int    g_counts[N_PTS];
__device__ __half g_y1h[(size_t)N_PTS * 64];   // pre-BN layer-1 output (fp16)
__device__ __half g_z[(size_t)N_PTS * 128];    // pre-BN layer-2 output (fp16)
__device__ float  g_stats1[2 * 64];            // weighted sum, sumsq
__device__ float  g_stats2[2 * 128];

// ---------------- packed f32x2 helpers --------------------------------------
__device__ __forceinline__ unsigned long long pack2s(float a) {
    unsigned long long r;
    asm("mov.b64 %0, {%1, %1};" : "=l"(r) : "f"(a));
    return r;
}
__device__ __forceinline__ float2 unpack2(unsigned long long v) {
    float2 r;
    asm("mov.b64 {%0, %1}, %2;" : "=f"(r.x), "=f"(r.y) : "l"(v));
    return r;
}
__device__ __forceinline__ void fma2(unsigned long long& d,
                                     unsigned long long a,
                                     unsigned long long b) {
    asm("fma.rn.f32x2 %0, %1, %2, %0;" : "+l"(d) : "l"(a), "l"(b));
}

// ---------------- small kernels ----------------------------------------------
__global__ void zero_kernel() {
    int i = blockIdx.x * blockDim.x + threadIdx.x;
    if (i < N_PTS) g_counts[i] = 0;
    if (i < 2 * 64) g_stats1[i] = 0.f;
    if (i < 2 * 128) g_stats2[i] = 0.f;
}

__global__ void count_kernel(const int4* __restrict__ idx4) {
    int i = blockIdx.x * blockDim.x + threadIdx.x;
    if (i < NK / 4) {
        int4 v = idx4[i];
        atomicAdd(&g_counts[v.x], 1);
        atomicAdd(&g_counts[v.y], 1);
        atomicAdd(&g_counts[v.z], 1);
        atomicAdd(&g_counts[v.w], 1);
    }
}

// GEMM1: y1 = feat @ W1 + b1 ; weighted BN1 stats (on fp16-quantized y1).
// Block: 64 rows x 64 cols, 128 threads as 8(tx) x 16(ty); 6 CTAs/SM.
// Thread tile: 4 rows x 8 cols ({tx*4..+3, 32+tx*4..+3}).
__global__ __launch_bounds__(128, 6) void gemm1_kernel(const float* __restrict__ feat,
                                                       const float* __restrict__ W1,
                                                       const float* __restrict__ b1) {
    __shared__ float As[64 * ASTRIDE];   // ~17 KB, [row][k] padded
    __shared__ float Bs[64 * 64];        // 16 KB, [k][col]
    const int tid = threadIdx.x;
    const int tx = tid & 7, ty = tid >> 3;     // ty 0..15
    const int row0 = blockIdx.x * 64;

#pragma unroll
    for (int it = 0; it < 8; it++) {
        int f = tid + it * 128;
        ((float4*)Bs)[f] = ((const float4*)W1)[f];
    }
#pragma unroll
    for (int it = 0; it < 8; it++) {
        int f = tid + it * 128;          // [0, 1024)
        int r = f >> 4, k4 = f & 15;
        int grow = row0 + r;
        float4 v = (grow < N_PTS) ? ((const float4*)feat)[grow * 16 + k4]
                                  : make_float4(0.f, 0.f, 0.f, 0.f);
        *(float4*)&As[r * ASTRIDE + k4 * 4] = v;
    }
    __syncthreads();

    unsigned long long acc[4][4];
#pragma unroll
    for (int i = 0; i < 4; i++)
#pragma unroll
        for (int j = 0; j < 4; j++) acc[i][j] = 0ull;

#pragma unroll
    for (int kk = 0; kk < 64; kk += 2) {
        float2 a[4];
#pragma unroll
        for (int i = 0; i < 4; i++)
            a[i] = *(const float2*)&As[(ty * 4 + i) * ASTRIDE + kk];
#pragma unroll
        for (int kq = 0; kq < 2; kq++) {
            const ulonglong2 bA = *(const ulonglong2*)&Bs[(kk + kq) * 64 + tx * 4];
            const ulonglong2 bB = *(const ulonglong2*)&Bs[(kk + kq) * 64 + 32 + tx * 4];
#pragma unroll
            for (int i = 0; i < 4; i++) {
                unsigned long long ad = pack2s(kq ? a[i].y : a[i].x);
                fma2(acc[i][0], ad, bA.x);
                fma2(acc[i][1], ad, bA.y);
                fma2(acc[i][2], ad, bB.x);
                fma2(acc[i][3], ad, bB.y);
            }
        }
    }

    const float4 biasA = *(const float4*)&b1[tx * 4];
    const float4 biasB = *(const float4*)&b1[32 + tx * 4];
    float ws[8], wq[8];
#pragma unroll
    for (int j = 0; j < 8; j++) { ws[j] = 0.f; wq[j] = 0.f; }
#pragma unroll
    for (int i = 0; i < 4; i++) {
        int grow = row0 + ty * 4 + i;
        if (grow >= N_PTS) continue;
        float2 p0 = unpack2(acc[i][0]);
        float2 p1 = unpack2(acc[i][1]);
        float2 p2 = unpack2(acc[i][2]);
        float2 p3 = unpack2(acc[i][3]);
        // quantize to fp16 (stored value) and compute stats on the quantized
        // values so BN1 stats match what gemm2 will actually normalize.
        __half2 h0 = __floats2half2_rn(p0.x + biasA.x, p0.y + biasA.y);
        __half2 h1 = __floats2half2_rn(p1.x + biasA.z, p1.y + biasA.w);
        __half2 h2 = __floats2half2_rn(p2.x + biasB.x, p2.y + biasB.y);
        __half2 h3 = __floats2half2_rn(p3.x + biasB.z, p3.y + biasB.w);
        uint2 hv0, hv1;
        hv0.x = *(uint32_t*)&h0; hv0.y = *(uint32_t*)&h1;
        hv1.x = *(uint32_t*)&h2; hv1.y = *(uint32_t*)&h3;
        *(uint2*)&g_y1h[(size_t)grow * 64 + tx * 4] = hv0;
        *(uint2*)&g_y1h[(size_t)grow * 64 + 32 + tx * 4] = hv1;
        float2 q0 = __half22float2(h0);
        float2 q1 = __half22float2(h1);
        float2 q2 = __half22float2(h2);
        float2 q3 = __half22float2(h3);
        float y[8] = {q0.x, q0.y, q1.x, q1.y, q2.x, q2.y, q3.x, q3.y};
        float w = (float)g_counts[grow];
#pragma unroll
        for (int j = 0; j < 8; j++) {
            ws[j] += w * y[j];
            wq[j] += w * y[j] * y[j];
        }
    }
    __syncthreads();
    float* red = As;
#pragma unroll
    for (int j = 0; j < 4; j++) {
        red[ty * 64 + tx * 4 + j] = ws[j];
        red[ty * 64 + 32 + tx * 4 + j] = ws[4 + j];
        red[1024 + ty * 64 + tx * 4 + j] = wq[j];
        red[1024 + ty * 64 + 32 + tx * 4 + j] = wq[4 + j];
    }
    __syncthreads();
    if (tid < 64) {
        float s = 0.f, q = 0.f;
#pragma unroll
        for (int t = 0; t < 16; t++) {
            s += red[t * 64 + tid];
            q += red[1024 + t * 64 + tid];
        }
        atomicAdd(&g_stats1[tid], s);
        atomicAdd(&g_stats1[64 + tid], q);
    }
}

// GEMM2: h = relu(bn1(y1)); y2 = h @ W2 + b2 -> fp16 g_z; weighted BN2 stats.
// Block: 64 rows x 64 cols (blockIdx.y = N-half), 128 threads as 16(tx) x 8(ty).
// Thread tile: 8 rows ({ty*4+i, 32+ty*4+i}) x 4 cols; 6 CTAs/SM.  (R12 shape)
__global__ __launch_bounds__(128, 6) void gemm2_kernel(const float* __restrict__ W2,
                                                       const float* __restrict__ b2,
                                                       const float* __restrict__ gamma1,
                                                       const float* __restrict__ beta1) {
    __shared__ float As[64 * ASTRIDE];   // ~17 KB, [row][k] padded
    __shared__ float Bs[64 * 64];        // 16 KB, [k][col-half]
    __shared__ float sb1s[128];
    const int tid = threadIdx.x;
    const int tx = tid & 15, ty = tid >> 4;    // ty 0..7
    const int row0 = blockIdx.x * 64;
    const int col0 = blockIdx.y * 64;

    if (tid < 64) {
        const float inv_m = 1.0f / (float)NK;
        float mean = g_stats1[tid] * inv_m;
        float var = g_stats1[64 + tid] * inv_m - mean * mean;
        float sc = gamma1[tid] * rsqrtf(var + EPSB);
        sb1s[tid] = sc;
        sb1s[64 + tid] = beta1[tid] - mean * sc;
    }
    // B half: Bs[k][0..63] = W2[k][col0..col0+63]
#pragma unroll
    for (int it = 0; it < 8; it++) {
        int f = tid + it * 128;           // k = f>>4, c4 = f&15
        int k = f >> 4, c4 = f & 15;
        ((float4*)Bs)[f] = *(const float4*)&W2[k * 128 + col0 + c4 * 4];
    }
    __syncthreads();   // sb1s ready

#pragma unroll
    for (int it = 0; it < 8; it++) {
        int f = tid + it * 128;          // [0, 1024)
        int r = f >> 4, k4 = f & 15;
        int grow = row0 + r;
        uint2 hv = make_uint2(0u, 0u);
        if (grow < N_PTS)
            hv = *(const uint2*)&g_y1h[(size_t)grow * 64 + k4 * 4];
        __half2* ph = (__half2*)&hv;
        float2 f01 = __half22float2(ph[0]);
        float2 f23 = __half22float2(ph[1]);
        float4 v = make_float4(f01.x, f01.y, f23.x, f23.y);
        float4 s = *(const float4*)&sb1s[k4 * 4];
        float4 bb = *(const float4*)&sb1s[64 + k4 * 4];
        v.x = fmaxf(fmaf(v.x, s.x, bb.x), 0.f);
        v.y = fmaxf(fmaf(v.y, s.y, bb.y), 0.f);
        v.z = fmaxf(fmaf(v.z, s.z, bb.z), 0.f);
        v.w = fmaxf(fmaf(v.w, s.w, bb.w), 0.f);
        *(float4*)&As[r * ASTRIDE + k4 * 4] = v;
    }
    __syncthreads();

    unsigned long long acc[8][2];
#pragma unroll
    for (int i = 0; i < 8; i++) { acc[i][0] = 0ull; acc[i][1] = 0ull; }

#pragma unroll
    for (int kk = 0; kk < 64; kk += 2) {
        float2 a[8];
#pragma unroll
        for (int i = 0; i < 4; i++) {
            a[i]     = *(const float2*)&As[(ty * 4 + i) * ASTRIDE + kk];
            a[4 + i] = *(const float2*)&As[(32 + ty * 4 + i) * ASTRIDE + kk];
        }
#pragma unroll
        for (int kq = 0; kq < 2; kq++) {
            const ulonglong2 bA = *(const ulonglong2*)&Bs[(kk + kq) * 64 + tx * 4];
#pragma unroll
            for (int i = 0; i < 8; i++) {
                unsigned long long ad = pack2s(kq ? a[i].y : a[i].x);
                fma2(acc[i][0], ad, bA.x);
                fma2(acc[i][1], ad, bA.y);
            }
        }
    }

    const float4 biasA = *(const float4*)&b2[col0 + tx * 4];
    float ws[4] = {0.f, 0.f, 0.f, 0.f}, wq[4] = {0.f, 0.f, 0.f, 0.f};
#pragma unroll
    for (int i = 0; i < 8; i++) {
        int grow = row0 + ((i < 4) ? (ty * 4 + i) : (32 + ty * 4 + (i - 4)));
        if (grow >= N_PTS) continue;
        float2 p0 = unpack2(acc[i][0]);
        float2 p1 = unpack2(acc[i][1]);
        float y0 = p0.x + biasA.x, y1v = p0.y + biasA.y;
        float y2v = p1.x + biasA.z, y3 = p1.y + biasA.w;
        __half2 h0 = __floats2half2_rn(y0, y1v);
        __half2 h1 = __floats2half2_rn(y2v, y3);
        uint2 hv;
        hv.x = *(uint32_t*)&h0;
        hv.y = *(uint32_t*)&h1;
        *(uint2*)&g_z[(size_t)grow * 128 + col0 + tx * 4] = hv;
        float w = (float)g_counts[grow];
        ws[0] += w * y0;  wq[0] += w * y0 * y0;
        ws[1] += w * y1v; wq[1] += w * y1v * y1v;
        ws[2] += w * y2v; wq[2] += w * y2v * y2v;
        ws[3] += w * y3;  wq[3] += w * y3 * y3;
    }
    __syncthreads();
    float* red = As;  // need 2 * 512 floats
#pragma unroll
    for (int j = 0; j < 4; j++) {
        red[ty * 64 + tx * 4 + j] = ws[j];
        red[512 + ty * 64 + tx * 4 + j] = wq[j];
    }
    __syncthreads();
    if (tid < 64) {
        float s = 0.f, q = 0.f;
#pragma unroll
        for (int t = 0; t < 8; t++) {
            s += red[t * 64 + tid];
            q += red[512 + t * 64 + tid];
        }
        atomicAdd(&g_stats2[col0 + tid], s);
        atomicAdd(&g_stats2[128 + col0 + tid], q);
    }
}

// Final gather + max/min-pool over pre-BN fp16 table, then folded BN2
// affine + ReLU (per-thread from g_stats2). One warp = TWO points.
__global__ __launch_bounds__(256) void gather_max_kernel(
    const int* __restrict__ idx, const float* __restrict__ gamma2,
    const float* __restrict__ beta2, float* __restrict__ out) {
    int warp = (blockIdx.x * blockDim.x + threadIdx.x) >> 5;
    int lane = threadIdx.x & 31;
    int p = warp * 2 + (lane >> 4);
    if (p >= N_PTS) return;
    int half_lane = lane & 15;
    int c0 = half_lane * 8;

    int myidx = idx[p * 16 + half_lane];

    __half2 mx[4], mn[4];
#pragma unroll
    for (int j = 0; j < 4; j++) {
        mx[j] = __floats2half2_rn(-65504.f, -65504.f);
        mn[j] = __floats2half2_rn(65504.f, 65504.f);
    }

#pragma unroll
    for (int k = 0; k < 16; k++) {
        int r = __shfl_sync(0xffffffffu, myidx, (lane & 16) + k);
        uint4 raw = *(const uint4*)&g_z[(size_t)r * 128 + c0];
        __half2 v[4];
        *(uint4*)v = raw;
        mx[0] = __hmax2(mx[0], v[0]); mn[0] = __hmin2(mn[0], v[0]);
        mx[1] = __hmax2(mx[1], v[1]); mn[1] = __hmin2(mn[1], v[1]);
        mx[2] = __hmax2(mx[2], v[2]); mn[2] = __hmin2(mn[2], v[2]);
        mx[3] = __hmax2(mx[3], v[3]); mn[3] = __hmin2(mn[3], v[3]);
    }

    const float inv_m = 1.0f / (float)NK;
    float4 sum0 = *(const float4*)&g_stats2[c0];
    float4 sum1 = *(const float4*)&g_stats2[c0 + 4];
    float4 sq0 = *(const float4*)&g_stats2[128 + c0];
    float4 sq1 = *(const float4*)&g_stats2[128 + c0 + 4];
    float4 gm0 = *(const float4*)&gamma2[c0];
    float4 gm1 = *(const float4*)&gamma2[c0 + 4];
    float4 bt0 = *(const float4*)&beta2[c0];
    float4 bt1 = *(const float4*)&beta2[c0 + 4];
    float sm[8] = {sum0.x, sum0.y, sum0.z, sum0.w, sum1.x, sum1.y, sum1.z, sum1.w};
    float sq[8] = {sq0.x, sq0.y, sq0.z, sq0.w, sq1.x, sq1.y, sq1.z, sq1.w};
    float gm[8] = {gm0.x, gm0.y, gm0.z, gm0.w, gm1.x, gm1.y, gm1.z, gm1.w};
    float bt[8] = {bt0.x, bt0.y, bt0.z, bt0.w, bt1.x, bt1.y, bt1.z, bt1.w};

    float o[8];
#pragma unroll
    for (int j = 0; j < 8; j++) {
        float mean = sm[j] * inv_m;
        float var = sq[j] * inv_m - mean * mean;
        float sc = gm[j] * rsqrtf(var + EPSB);
        float bi = bt[j] - mean * sc;
        float2 fx = __half22float2(mx[j >> 1]);
        float2 fn = __half22float2(mn[j >> 1]);
        float vx = (j & 1) ? fx.y : fx.x;
        float vn = (j & 1) ? fn.y : fn.x;
        float m = (sc >= 0.f) ? vx : vn;
        o[j] = fmaxf(fmaf(sc, m, bi), 0.f);
    }
    size_t off = (size_t)p * 128 + c0;
    *(float4*)&out[off]     = make_float4(o[0], o[1], o[2], o[3]);
    *(float4*)&out[off + 4] = make_float4(o[4], o[5], o[6], o[7]);
}

// ---------------- launch ------------------------------------------------------
extern "C" void kernel_launch(void* const* d_in, const int* in_sizes, int n_in,
                              void* d_out, int out_size) {
    const float* feat = (const float*)d_in[0];
    const int* idx = (const int*)d_in[1];
    const float* W1 = (const float*)d_in[2];
    const float* b1 = (const float*)d_in[3];
    const float* g1 = (const float*)d_in[4];
    const float* be1 = (const float*)d_in[5];
    const float* W2 = (const float*)d_in[6];
    const float* b2 = (const float*)d_in[7];
    const float* g2 = (const float*)d_in[8];
    const float* be2 = (const float*)d_in[9];
    float* out = (float*)d_out;

    zero_kernel<<<(N_PTS + 255) / 256, 256>>>();
    count_kernel<<<(NK / 4 + 255) / 256, 256>>>((const int4*)idx);
    gemm1_kernel<<<(N_PTS + 63) / 64, 128>>>(feat, W1, b1);
    dim3 g2grid((N_PTS + 63) / 64, 2);
    gemm2_kernel<<<g2grid, 128>>>(W2, b2, g1, be1);
    gather_max_kernel<<<(N_PTS * 16 + 255) / 256, 256>>>(idx, g2, be2, out);
}